// round 11
// baseline (speedup 1.0000x reference)
#include <cuda_runtime.h>
#include <cuda_fp16.h>
#include <cstdint>

#define Bc   16
#define Nn   10000
#define Mrows (Bc*Nn)   // 160000
#define NTILES (Mrows/128)   // 1250
#define GRID 148

__device__ __forceinline__ uint32_t smem_u32(const void* p) {
    uint32_t a;
    asm("{ .reg .u64 t; cvta.to.shared.u64 t, %1; cvt.u32.u64 %0, t; }" : "=r"(a) : "l"(p));
    return a;
}

// Wv pre-converted to fp16, [k][c] (c = 0..255, heads contiguous)
__device__ __half g_Bh[(size_t)256 * 256];

// ======================= fused GEMM + LayerNorm =============================
// out = LN_perhead(x @ Wv), permuted row write. Retention weight w cancels
// through LN (w>0, eps/w^2 ~1e-6 rel). Single-pass fp16 == exact GEMM against
// fp16-quantized x and Wv; rel err ~2.8e-4 (gate 1e-3).
// Persistent: 148 CTAs x 512 thr; B resident (128KB); A staged via cp.async
// (2x16KB ring, 2 chunks ahead) and converted thread-locally to fp16.
#define SM_B    0
#define SM_A    131072
#define SM_S    (131072 + 65536)
#define SM_TOT  (131072 + 65536 + 32768)   // 229376 B = 224KB

__device__ __forceinline__ void ldsm_x4(uint32_t* r, uint32_t addr) {
    asm volatile("ldmatrix.sync.aligned.m8n8.x4.shared.b16 {%0,%1,%2,%3}, [%4];"
                 : "=r"(r[0]), "=r"(r[1]), "=r"(r[2]), "=r"(r[3]) : "r"(addr));
}
__device__ __forceinline__ void ldsm_x4t(uint32_t* r, uint32_t addr) {
    asm volatile("ldmatrix.sync.aligned.m8n8.x4.trans.shared.b16 {%0,%1,%2,%3}, [%4];"
                 : "=r"(r[0]), "=r"(r[1]), "=r"(r[2]), "=r"(r[3]) : "r"(addr));
}
__device__ __forceinline__ void mma16816(float* c, const uint32_t* a, const uint32_t* b) {
    asm volatile("mma.sync.aligned.m16n8k16.row.col.f32.f16.f16.f32 "
                 "{%0,%1,%2,%3}, {%4,%5,%6,%7}, {%8,%9}, {%0,%1,%2,%3};"
                 : "+f"(c[0]), "+f"(c[1]), "+f"(c[2]), "+f"(c[3])
                 : "r"(a[0]), "r"(a[1]), "r"(a[2]), "r"(a[3]), "r"(b[0]), "r"(b[1]));
}
#define CP_ASYNC16(dst, src) \
    asm volatile("cp.async.ca.shared.global [%0], [%1], 16;" :: "r"(dst), "l"(src))
#define CP_COMMIT()  asm volatile("cp.async.commit_group;")
#define CP_WAIT0()   asm volatile("cp.async.wait_group 0;")
#define CP_WAIT1()   asm volatile("cp.async.wait_group 1;")

// ---- Wv -> fp16 (1:1 layout) ----
__global__ void convert_b_kernel(const float* __restrict__ Wv) {
    int idx = blockIdx.x * 256 + threadIdx.x;   // 65536 total
    g_Bh[idx] = __float2half_rn(Wv[idx]);
}

__global__ __launch_bounds__(512, 1) void gemm_ln_kernel(
    const float* __restrict__ x,
    const float* __restrict__ lgamma, const float* __restrict__ lbeta,
    float* __restrict__ out)
{
    extern __shared__ __align__(16) char smem[];
    const uint32_t sbB = smem_u32(smem + SM_B);
    const uint32_t sbA = smem_u32(smem + SM_A);
    const uint32_t sbS = smem_u32(smem + SM_S);

    const int tid  = threadIdx.x;
    const int lane = tid & 31;
    const int wid  = tid >> 5;
    const int wm   = wid & 3;      // 4 M-groups of 32 rows
    const int head = wid >> 2;     // 4 heads of 64 cols

    // ---- B fill once: whole Wv fp16, 8192 x 16B via cp.async (group 0) ----
#pragma unroll
    for (int it = 0; it < 16; ++it) {
        int seg = tid + it * 512;
        int k   = seg >> 5;
        int ch  = seg & 31;
        CP_ASYNC16(sbB + (uint32_t)(k * 512 + ((ch ^ (k & 7)) << 4)),
                   (const void*)(g_Bh + k * 256 + ch * 8));
    }
    CP_COMMIT();

    // ---- stage helpers: chunk = 16 rows x 256 fp32 = 16KB; thread owns 32B ----
    const uint32_t sOff = (uint32_t)(tid * 32);
    // prefetch chunks 0,1 of first tile
    {
        const float* xt = x + (size_t)blockIdx.x * 32768;
        CP_ASYNC16(sbS + sOff,      (const void*)(xt + tid * 8));
        CP_ASYNC16(sbS + sOff + 16, (const void*)(xt + tid * 8 + 4));
        CP_COMMIT();
        CP_ASYNC16(sbS + 16384 + sOff,      (const void*)(xt + 4096 + tid * 8));
        CP_ASYNC16(sbS + 16384 + sOff + 16, (const void*)(xt + 4096 + tid * 8 + 4));
        CP_COMMIT();
    }

    // ---- lane-constant MMA address pieces ----
    const int hi4 = lane >> 4;
    const int bt  = lane >> 3;
    const int klane = ((bt & 1) << 3) + (lane & 7);
    const int cb0   = head * 8 + (bt >> 1);
    uint32_t aRow[2]; int aR7[2];
#pragma unroll
    for (int mb = 0; mb < 2; ++mb) {
        int row = wm * 32 + mb * 16 + (lane & 15);
        aRow[mb] = sbA + (uint32_t)(row * 512);
        aR7[mb]  = row & 7;
    }
    uint32_t bBase[4];
#pragma unroll
    for (int nb16 = 0; nb16 < 4; ++nb16) {
        int ch = cb0 + nb16 * 2;
        bBase[nb16] = sbB + (uint32_t)(klane * 512 + ((ch ^ (klane & 7)) << 4));
    }
    // convert-phase constants
    const int arow_l = tid >> 5;           // row within chunk (0..15)
    const int achk   = tid & 31;           // 16B chunk within row
    const uint32_t aSts = sbA + (uint32_t)(((achk ^ ((arow_l)&7)) & 0) /*placeholder*/);

    // ---- persistent tile loop ----
    for (int t = blockIdx.x; t < NTILES; t += GRID) {
        const int tnext = (t + GRID < NTILES) ? t + GRID : t;   // clamped prefetch
        const float* xt  = x + (size_t)t * 32768;
        const float* xtn = x + (size_t)tnext * 32768;
        const int m0 = t * 128;

        // ---- convert 8 chunks, prefetch 2 ahead ----
#pragma unroll
        for (int c = 0; c < 8; ++c) {
            CP_WAIT1();   // own segs of chunk c landed (c+1 in flight)
            const uint32_t sb = sbS + (uint32_t)((c & 1) * 16384) + sOff;
            float4 a0 = *(const float4*)(smem + SM_S + (c & 1) * 16384 + tid * 32);
            float4 a1 = *(const float4*)(smem + SM_S + (c & 1) * 16384 + tid * 32 + 16);
            const int row = c * 16 + arow_l;
            __half2 p0 = __floats2half2_rn(a0.x, a0.y);
            __half2 p1 = __floats2half2_rn(a0.z, a0.w);
            __half2 p2 = __floats2half2_rn(a1.x, a1.y);
            __half2 p3 = __floats2half2_rn(a1.z, a1.w);
            uint4 pk;
            pk.x = *(uint32_t*)&p0; pk.y = *(uint32_t*)&p1;
            pk.z = *(uint32_t*)&p2; pk.w = *(uint32_t*)&p3;
            *(uint4*)(smem + SM_A + row * 512 + ((achk ^ (row & 7)) << 4)) = pk;
            // issue chunk c+2 into the buffer just freed
            const int cc = c + 2;
            const float* src = (cc < 8) ? (xt + cc * 4096 + tid * 8)
                                        : (xtn + (cc - 8) * 4096 + tid * 8);
            CP_ASYNC16(sb, (const void*)src);
            CP_ASYNC16(sb + 16, (const void*)(src + 4));
            CP_COMMIT();
        }
        __syncthreads();   // A tile fully written (B landed long before)

        // ---- MMA: 16 x (6 LDSM -> 16 MMA) ----
        float C[2][8][4];
#pragma unroll
        for (int mb = 0; mb < 2; ++mb)
#pragma unroll
            for (int nb = 0; nb < 8; ++nb)
#pragma unroll
                for (int r = 0; r < 4; ++r) C[mb][nb][r] = 0.f;

#pragma unroll 4
        for (int k16 = 0; k16 < 16; ++k16) {
            uint32_t af[2][4], bf[4][4];
#pragma unroll
            for (int mb = 0; mb < 2; ++mb) {
                int chA = k16 * 2 + hi4;
                ldsm_x4(af[mb], aRow[mb] + (uint32_t)((chA ^ aR7[mb]) << 4));
            }
#pragma unroll
            for (int nb16 = 0; nb16 < 4; ++nb16)
                ldsm_x4t(bf[nb16], bBase[nb16] + (uint32_t)(k16 * 8192));
#pragma unroll
            for (int mb = 0; mb < 2; ++mb)
#pragma unroll
                for (int nb = 0; nb < 8; ++nb)
                    mma16816(C[mb][nb], af[mb], &bf[nb >> 1][(nb & 1) * 2]);
        }
        __syncthreads();   // A free for next tile's converts

        // ---- warp-local LayerNorm + permuted store ----
        float g0[8], g1[8], be0[8], be1[8];
#pragma unroll
        for (int nb = 0; nb < 8; ++nb) {
            int dv = nb * 8 + (lane & 3) * 2;
            g0[nb]  = lgamma[dv];  g1[nb]  = lgamma[dv + 1];
            be0[nb] = lbeta[dv];   be1[nb] = lbeta[dv + 1];
        }
#pragma unroll
        for (int mb = 0; mb < 2; ++mb)
#pragma unroll
            for (int half = 0; half < 2; ++half) {
                float s = 0.f, q = 0.f;
#pragma unroll
                for (int nb = 0; nb < 8; ++nb) {
                    float v0 = C[mb][nb][2 * half];
                    float v1 = C[mb][nb][2 * half + 1];
                    s += v0 + v1;
                    q += v0 * v0 + v1 * v1;
                }
                s += __shfl_xor_sync(0xffffffffu, s, 1);
                q += __shfl_xor_sync(0xffffffffu, q, 1);
                s += __shfl_xor_sync(0xffffffffu, s, 2);
                q += __shfl_xor_sync(0xffffffffu, q, 2);
                const float mu   = s * (1.0f / 64.0f);
                const float var  = q * (1.0f / 64.0f) - mu * mu;
                const float rstd = rsqrtf(fmaxf(var, 0.f) + 1e-30f);

                const int m    = m0 + wm * 32 + mb * 16 + half * 8 + (lane >> 2);
                const int orow = (m & 15) * Nn + (m >> 4);
                float* obase = out + (size_t)orow * 256 + head * 64;
#pragma unroll
                for (int nb = 0; nb < 8; ++nb) {
                    int c = nb * 8 + (lane & 3) * 2;
                    float v0 = (C[mb][nb][2 * half]     - mu) * rstd * g0[nb] + be0[nb];
                    float v1 = (C[mb][nb][2 * half + 1] - mu) * rstd * g1[nb] + be1[nb];
                    *(float2*)(obase + c) = make_float2(v0, v1);
                }
            }
    }
    CP_WAIT0();   // drain any clamped prefetches before exit
}

// ======================= launch =============================================
extern "C" void kernel_launch(void* const* d_in, const int* in_sizes, int n_in,
                              void* d_out, int out_size)
{
    const float* x  = (const float*)d_in[0];
    const float* Wv = (const float*)d_in[4];
    const float* lg = (const float*)d_in[5];
    const float* lb = (const float*)d_in[6];
    float* out = (float*)d_out;
    (void)in_sizes; (void)n_in; (void)out_size;

    cudaFuncSetAttribute(gemm_ln_kernel,
                         cudaFuncAttributeMaxDynamicSharedMemorySize, SM_TOT);

    convert_b_kernel<<<256, 256>>>(Wv);
    gemm_ln_kernel<<<GRID, 512, SM_TOT>>>(x, lg, lb, out);
}

// round 12
// speedup vs baseline: 1.0018x; 1.0018x over previous
#include <cuda_runtime.h>
#include <cuda_fp16.h>
#include <cstdint>

#define Bc   16
#define Nn   10000
#define Mrows (Bc*Nn)      // 160000
#define MT   96            // rows per CTA
#define NT   ((Mrows + MT - 1) / MT)   // 1667 row tiles
#define GRIDX (2 * NT)     // x2 head-pairs

__device__ __forceinline__ uint32_t smem_u32(const void* p) {
    uint32_t a;
    asm("{ .reg .u64 t; cvta.to.shared.u64 t, %1; cvt.u32.u64 %0, t; }" : "=r"(a) : "l"(p));
    return a;
}

// Wv pre-converted to fp16, [k][c] (c = 0..255)
__device__ __half g_Bh[(size_t)256 * 256];

// ======================= fused GEMM + LayerNorm =============================
// out = LN_perhead(x @ Wv), permuted row write. Retention weight w cancels
// through LN (w>0, eps/w^2 ~1e-6 rel). Single-pass fp16 == exact GEMM against
// fp16-quantized x and Wv; rel err ~2.8e-4 (gate 1e-3).
// CTA: 96 rows x 128 cols (one head-pair). 384 thr = 12 warps = 3 wm x 4 cn,
// warp tile 32x32. B resident 64KB (loaded once), A 48KB. 2 CTAs/SM, 24 warps.
#define SM_B   0
#define SM_A   65536
#define SM_TOT (65536 + 49152)   // 112KB

__device__ __forceinline__ void ldsm_x4(uint32_t* r, uint32_t addr) {
    asm volatile("ldmatrix.sync.aligned.m8n8.x4.shared.b16 {%0,%1,%2,%3}, [%4];"
                 : "=r"(r[0]), "=r"(r[1]), "=r"(r[2]), "=r"(r[3]) : "r"(addr));
}
__device__ __forceinline__ void ldsm_x4t(uint32_t* r, uint32_t addr) {
    asm volatile("ldmatrix.sync.aligned.m8n8.x4.trans.shared.b16 {%0,%1,%2,%3}, [%4];"
                 : "=r"(r[0]), "=r"(r[1]), "=r"(r[2]), "=r"(r[3]) : "r"(addr));
}
__device__ __forceinline__ void mma16816(float* c, const uint32_t* a, const uint32_t* b) {
    asm volatile("mma.sync.aligned.m16n8k16.row.col.f32.f16.f16.f32 "
                 "{%0,%1,%2,%3}, {%4,%5,%6,%7}, {%8,%9}, {%0,%1,%2,%3};"
                 : "+f"(c[0]), "+f"(c[1]), "+f"(c[2]), "+f"(c[3])
                 : "r"(a[0]), "r"(a[1]), "r"(a[2]), "r"(a[3]), "r"(b[0]), "r"(b[1]));
}
#define CP_ASYNC16(dst, src) \
    asm volatile("cp.async.ca.shared.global [%0], [%1], 16;" :: "r"(dst), "l"(src))
#define CP_COMMIT()  asm volatile("cp.async.commit_group;")
#define CP_WAIT0()   asm volatile("cp.async.wait_group 0;")

// ---- Wv -> fp16 (1:1 layout) ----
__global__ void convert_b_kernel(const float* __restrict__ Wv) {
    int idx = blockIdx.x * 256 + threadIdx.x;   // 65536 total
    g_Bh[idx] = __float2half_rn(Wv[idx]);
}

__global__ __launch_bounds__(384, 2) void gemm_ln_kernel(
    const float* __restrict__ x,
    const float* __restrict__ lgamma, const float* __restrict__ lbeta,
    float* __restrict__ out)
{
    extern __shared__ __align__(16) char smem[];
    const uint32_t sbB = smem_u32(smem + SM_B);
    const uint32_t sbA = smem_u32(smem + SM_A);

    const int tid  = threadIdx.x;
    const int lane = tid & 31;
    const int wid  = tid >> 5;
    const int wm   = wid % 3;          // 3 row groups of 32
    const int cn   = wid / 3;          // 4 col groups of 32 (within 128)
    const int hb   = blockIdx.x & 1;   // head pair
    const int m0   = (blockIdx.x >> 1) * MT;

    // ---- B fill once: 256k x 128c fp16 = 64KB via cp.async (one group) ----
#pragma unroll
    for (int it = 0; it < 11; ++it) {
        int seg = tid + it * 384;               // 4096 x 16B
        if (seg < 4096) {
            int k  = seg >> 4;
            int ch = seg & 15;
            CP_ASYNC16(sbB + (uint32_t)(k * 256 + ((ch ^ (k & 7)) << 4)),
                       (const void*)(g_Bh + k * 256 + hb * 128 + ch * 8));
        }
    }
    CP_COMMIT();

    // ---- A fill: 96 x 256 fp32 -> fp16, XOR-swizzled (zero-pad OOB rows) ----
#pragma unroll 4
    for (int it = 0; it < 16; ++it) {
        int i    = tid + it * 384;              // 6144 float4 slots
        int row  = i >> 6;
        int c4   = (i & 63) << 2;
        float4 a = make_float4(0.f, 0.f, 0.f, 0.f);
        if (m0 + row < Mrows)
            a = *(const float4*)(x + (size_t)(m0 + row) * 256 + c4);
        int chunk = c4 >> 3;
        int hf    = (c4 >> 2) & 1;
        __half2 lo = __floats2half2_rn(a.x, a.y);
        __half2 hi = __floats2half2_rn(a.z, a.w);
        uint2 pk;
        pk.x = *(uint32_t*)&lo;
        pk.y = *(uint32_t*)&hi;
        *(uint2*)(smem + SM_A + row * 512 + ((chunk ^ (row & 7)) << 4) + hf * 8) = pk;
    }
    CP_WAIT0();
    __syncthreads();

    // ---- lane-constant address pieces ----
    const int hi4 = lane >> 4;
    const int bt  = lane >> 3;
    const int klane = ((bt & 1) << 3) + (lane & 7);
    const int choff = bt >> 1;
    uint32_t aRow[2]; int aR7[2];
#pragma unroll
    for (int mb = 0; mb < 2; ++mb) {
        int row = wm * 32 + mb * 16 + (lane & 15);
        aRow[mb] = sbA + (uint32_t)(row * 512);
        aR7[mb]  = row & 7;
    }
    uint32_t bBase[2];
#pragma unroll
    for (int nb16 = 0; nb16 < 2; ++nb16) {
        int ch = cn * 4 + nb16 * 2 + choff;
        bBase[nb16] = sbB + (uint32_t)(klane * 256 + ((ch ^ (klane & 7)) << 4));
    }

    float C[2][4][4];
#pragma unroll
    for (int mb = 0; mb < 2; ++mb)
#pragma unroll
        for (int nb = 0; nb < 4; ++nb)
#pragma unroll
            for (int r = 0; r < 4; ++r) C[mb][nb][r] = 0.f;

    // ---- K pass: 16 x (4 LDSM -> 8 MMA) ----
#pragma unroll 4
    for (int k16 = 0; k16 < 16; ++k16) {
        uint32_t af[2][4], bf[2][4];
#pragma unroll
        for (int mb = 0; mb < 2; ++mb) {
            int chA = k16 * 2 + hi4;
            ldsm_x4(af[mb], aRow[mb] + (uint32_t)((chA ^ aR7[mb]) << 4));
        }
#pragma unroll
        for (int nb16 = 0; nb16 < 2; ++nb16)
            ldsm_x4t(bf[nb16], bBase[nb16] + (uint32_t)(k16 * 4096));
#pragma unroll
        for (int mb = 0; mb < 2; ++mb)
#pragma unroll
            for (int nb = 0; nb < 4; ++nb)
                mma16816(C[mb][nb], af[mb], &bf[nb >> 1][(nb & 1) * 2]);
    }
    __syncthreads();   // A/B dead; reuse A region for LN partials

    // ---- LN partials: quad reduce -> smem exchange between cn pairs ----
    float2* part = (float2*)(smem + SM_A);   // [96 rows][4 cn]
#pragma unroll
    for (int mb = 0; mb < 2; ++mb)
#pragma unroll
        for (int half = 0; half < 2; ++half) {
            const int rl = wm * 32 + mb * 16 + half * 8 + (lane >> 2);
            float s = 0.f, q = 0.f;
#pragma unroll
            for (int nb = 0; nb < 4; ++nb) {
                float v0 = C[mb][nb][2 * half];
                float v1 = C[mb][nb][2 * half + 1];
                s += v0 + v1;
                q += v0 * v0 + v1 * v1;
            }
            s += __shfl_xor_sync(0xffffffffu, s, 1);
            q += __shfl_xor_sync(0xffffffffu, q, 1);
            s += __shfl_xor_sync(0xffffffffu, s, 2);
            q += __shfl_xor_sync(0xffffffffu, q, 2);
            if ((lane & 3) == 0) part[rl * 4 + cn] = make_float2(s, q);
        }
    __syncthreads();

    // ---- LN + permuted store ----
    const int head = hb * 2 + (cn >> 1);
    float g0[4], g1[4], be0[4], be1[4];
#pragma unroll
    for (int nb = 0; nb < 4; ++nb) {
        int dv = (cn & 1) * 32 + nb * 8 + (lane & 3) * 2;
        g0[nb]  = lgamma[dv];  g1[nb]  = lgamma[dv + 1];
        be0[nb] = lbeta[dv];   be1[nb] = lbeta[dv + 1];
    }
#pragma unroll
    for (int mb = 0; mb < 2; ++mb)
#pragma unroll
        for (int half = 0; half < 2; ++half) {
            const int rl = wm * 32 + mb * 16 + half * 8 + (lane >> 2);
            const int m  = m0 + rl;
            if (m < Mrows) {
                float2 pa = part[rl * 4 + (cn & 2)];       // cn pair: {0,1} or {2,3}
                float2 pb = part[rl * 4 + (cn & 2) + 1];
                float mu   = (pa.x + pb.x) * (1.0f / 64.0f);
                float var  = (pa.y + pb.y) * (1.0f / 64.0f) - mu * mu;
                float rstd = rsqrtf(fmaxf(var, 0.f) + 1e-30f);
                const int orow = (m & 15) * Nn + (m >> 4);
                float* obase = out + (size_t)orow * 256 + head * 64 + (cn & 1) * 32;
#pragma unroll
                for (int nb = 0; nb < 4; ++nb) {
                    int c = nb * 8 + (lane & 3) * 2;
                    float2 o;
                    o.x = (C[mb][nb][2 * half]     - mu) * rstd * g0[nb] + be0[nb];
                    o.y = (C[mb][nb][2 * half + 1] - mu) * rstd * g1[nb] + be1[nb];
                    __stcs((float2*)(obase + c), o);   // streaming: don't pollute L2
                }
            }
        }
}

// ======================= launch =============================================
extern "C" void kernel_launch(void* const* d_in, const int* in_sizes, int n_in,
                              void* d_out, int out_size)
{
    const float* x  = (const float*)d_in[0];
    const float* Wv = (const float*)d_in[4];
    const float* lg = (const float*)d_in[5];
    const float* lb = (const float*)d_in[6];
    float* out = (float*)d_out;
    (void)in_sizes; (void)n_in; (void)out_size;

    cudaFuncSetAttribute(gemm_ln_kernel,
                         cudaFuncAttributeMaxDynamicSharedMemorySize, SM_TOT);

    convert_b_kernel<<<256, 256>>>(Wv);
    gemm_ln_kernel<<<GRIDX, 384, SM_TOT>>>(x, lg, lb, out);
}

// round 13
// speedup vs baseline: 1.3652x; 1.3628x over previous
#include <cuda_runtime.h>
#include <cuda_fp16.h>
#include <cstdint>

#define Nn    10000
#define Mrows 160000
#define NTILE 2500          // 64-row tiles
#define GRID  148

__device__ __forceinline__ uint32_t smem_u32(const void* p) {
    uint32_t a;
    asm("{ .reg .u64 t; cvta.to.shared.u64 t, %1; cvt.u32.u64 %0, t; }" : "=r"(a) : "l"(p));
    return a;
}

// Wv pre-converted to fp16, [k][c] (c = 0..255)
__device__ __half g_Bh[(size_t)256 * 256];

// ======================= fused GEMM + LayerNorm (warp-specialized) ==========
// out = LN_perhead(x @ Wv), permuted row write. Retention weight w cancels
// through LN (w>0, eps/w^2 ~1e-6 rel). Single-pass fp16 == exact GEMM against
// fp16-quantized x and Wv; rel err ~2.8e-4 (gate 1e-3).
// 148 persistent CTAs x 384 thr: warps 0-7 consume (2 wm x 4 heads, 32x64
// tile), warps 8-11 produce (cp.async stage -> fp16 convert -> STS).
// B resident 128KB; A 2x32KB double buffer; stage 2x16KB. Named-barrier
// FULL/EMPTY handoff so DRAM, tensor, and stores overlap structurally.
#define SM_B   0
#define SM_A   131072        // 2 x 32768
#define SM_S   196608        // 2 x 16384
#define SM_TOT 229376

#define BAR_FULL0  1
#define BAR_EMPTY0 3
#define BCNT 384

__device__ __forceinline__ void bar_sync(int id) {
    asm volatile("bar.sync %0, %1;" :: "r"(id), "r"(BCNT) : "memory");
}
__device__ __forceinline__ void bar_arrive(int id) {
    asm volatile("bar.arrive %0, %1;" :: "r"(id), "r"(BCNT) : "memory");
}

__device__ __forceinline__ void ldsm_x4(uint32_t* r, uint32_t addr) {
    asm volatile("ldmatrix.sync.aligned.m8n8.x4.shared.b16 {%0,%1,%2,%3}, [%4];"
                 : "=r"(r[0]), "=r"(r[1]), "=r"(r[2]), "=r"(r[3]) : "r"(addr));
}
__device__ __forceinline__ void ldsm_x4t(uint32_t* r, uint32_t addr) {
    asm volatile("ldmatrix.sync.aligned.m8n8.x4.trans.shared.b16 {%0,%1,%2,%3}, [%4];"
                 : "=r"(r[0]), "=r"(r[1]), "=r"(r[2]), "=r"(r[3]) : "r"(addr));
}
__device__ __forceinline__ void mma16816(float* c, const uint32_t* a, const uint32_t* b) {
    asm volatile("mma.sync.aligned.m16n8k16.row.col.f32.f16.f16.f32 "
                 "{%0,%1,%2,%3}, {%4,%5,%6,%7}, {%8,%9}, {%0,%1,%2,%3};"
                 : "+f"(c[0]), "+f"(c[1]), "+f"(c[2]), "+f"(c[3])
                 : "r"(a[0]), "r"(a[1]), "r"(a[2]), "r"(a[3]), "r"(b[0]), "r"(b[1]));
}
#define CP_ASYNC16(dst, src) \
    asm volatile("cp.async.ca.shared.global [%0], [%1], 16;" :: "r"(dst), "l"(src))
#define CP_COMMIT()  asm volatile("cp.async.commit_group;")
#define CP_WAIT0()   asm volatile("cp.async.wait_group 0;")
#define CP_WAIT1()   asm volatile("cp.async.wait_group 1;")

// ---- Wv -> fp16 (1:1 layout) ----
__global__ void convert_b_kernel(const float* __restrict__ Wv) {
    int idx = blockIdx.x * 256 + threadIdx.x;   // 65536 total
    g_Bh[idx] = __float2half_rn(Wv[idx]);
}

__global__ __launch_bounds__(384, 1) void gemm_ln_kernel(
    const float* __restrict__ x,
    const float* __restrict__ lgamma, const float* __restrict__ lbeta,
    float* __restrict__ out)
{
    extern __shared__ __align__(16) char smem[];
    const uint32_t sbB = smem_u32(smem + SM_B);
    const uint32_t sbA = smem_u32(smem + SM_A);
    const uint32_t sbS = smem_u32(smem + SM_S);

    const int tid  = threadIdx.x;
    const int lane = tid & 31;
    const int wid  = tid >> 5;
    const int ntl  = (NTILE - blockIdx.x + GRID - 1) / GRID;   // tiles for this CTA
    const int lastT = blockIdx.x + (ntl - 1) * GRID;

    // ---- B fill (all threads): 8192 x 16B cp.async ----
    for (int it = 0; it < 22; ++it) {
        int seg = tid + it * 384;
        if (seg < 8192) {
            int k  = seg >> 5;
            int ch = seg & 31;
            CP_ASYNC16(sbB + (uint32_t)(k * 512 + ((ch ^ (k & 7)) << 4)),
                       (const void*)(g_Bh + k * 256 + ch * 8));
        }
    }
    CP_COMMIT();
    CP_WAIT0();
    __syncthreads();

    if (wid >= 8) {
        // =================== PRODUCER (warps 8-11) ===================
        const int p = tid - 256;                  // 0..127
        const int nchunks = ntl * 4;              // 16-row chunks

        // issue chunk ii into stage (ii&1)
        auto issue = [&](int ii) {
            int tt = blockIdx.x + (ii >> 2) * GRID;
            if (tt > lastT) tt = lastT;
            const float* src = x + (size_t)tt * 16384 + (ii & 3) * 4096;
            uint32_t dst = sbS + (uint32_t)((ii & 1) * 16384);
#pragma unroll
            for (int s = 0; s < 8; ++s) {
                int slot = p + s * 128;
                CP_ASYNC16(dst + (uint32_t)(slot * 16), (const void*)(src + slot * 4));
            }
            CP_COMMIT();
        };
        issue(0);
        issue(1);

        for (int i = 0; i < nchunks; ++i) {
            const int buf = (i >> 2) & 1;
            if ((i & 3) == 0 && (i >> 2) >= 2)
                bar_sync(BAR_EMPTY0 + buf);       // consumer freed this buffer
            if (i >= nchunks - 2) { CP_WAIT0(); } else { CP_WAIT1(); }
            // convert chunk i: stage (i&1) -> A[buf]
            const char* sB = smem + SM_S + (i & 1) * 16384;
            char* aB = smem + SM_A + buf * 32768;
            const int r0 = (i & 3) * 16;
#pragma unroll
            for (int s = 0; s < 8; ++s) {
                int slot = p + s * 128;
                float4 a = *(const float4*)(sB + slot * 16);
                int row = r0 + (slot >> 6);
                int c4  = (slot & 63) << 2;
                int ch  = c4 >> 3;
                int hf  = (c4 >> 2) & 1;
                __half2 lo = __floats2half2_rn(a.x, a.y);
                __half2 hi = __floats2half2_rn(a.z, a.w);
                uint2 pk;
                pk.x = *(uint32_t*)&lo;
                pk.y = *(uint32_t*)&hi;
                *(uint2*)(aB + row * 512 + ((ch ^ (row & 7)) << 4) + hf * 8) = pk;
            }
            if ((i & 3) == 3) {
                __threadfence_block();
                bar_arrive(BAR_FULL0 + buf);      // buffer ready
            }
            int ii = i + 2;
            if (ii < nchunks) issue(ii);
        }
        CP_WAIT0();   // drain before exit
    } else {
        // =================== CONSUMER (warps 0-7) ===================
        const int wm   = wid & 1;     // 2 row groups of 32
        const int head = wid >> 1;    // 4 heads of 64 cols

        const int hi4 = lane >> 4;
        const int bt  = lane >> 3;
        const int klane = ((bt & 1) << 3) + (lane & 7);
        const int cb0   = head * 8 + (bt >> 1);
        uint32_t aRowOff[2]; int aR7[2];
#pragma unroll
        for (int mb = 0; mb < 2; ++mb) {
            int row = wm * 32 + mb * 16 + (lane & 15);
            aRowOff[mb] = (uint32_t)(row * 512);
            aR7[mb]     = row & 7;
        }
        uint32_t bBase[4];
#pragma unroll
        for (int nb16 = 0; nb16 < 4; ++nb16) {
            int ch = cb0 + nb16 * 2;
            bBase[nb16] = sbB + (uint32_t)(klane * 512 + ((ch ^ (klane & 7)) << 4));
        }
        float g0[8], g1[8], be0[8], be1[8];
#pragma unroll
        for (int nb = 0; nb < 8; ++nb) {
            int dv = nb * 8 + (lane & 3) * 2;
            g0[nb]  = lgamma[dv];  g1[nb]  = lgamma[dv + 1];
            be0[nb] = lbeta[dv];   be1[nb] = lbeta[dv + 1];
        }

        int lt = 0;
        for (int t = blockIdx.x; t < NTILE; t += GRID, ++lt) {
            const int buf = lt & 1;
            bar_sync(BAR_FULL0 + buf);            // A[buf] ready
            const uint32_t aB = sbA + (uint32_t)(buf * 32768);

            float C[2][8][4];
#pragma unroll
            for (int mb = 0; mb < 2; ++mb)
#pragma unroll
                for (int nb = 0; nb < 8; ++nb)
#pragma unroll
                    for (int r = 0; r < 4; ++r) C[mb][nb][r] = 0.f;

#pragma unroll 4
            for (int k16 = 0; k16 < 16; ++k16) {
                uint32_t af[2][4], bf[4][4];
#pragma unroll
                for (int mb = 0; mb < 2; ++mb) {
                    int chA = k16 * 2 + hi4;
                    ldsm_x4(af[mb], aB + aRowOff[mb] + (uint32_t)((chA ^ aR7[mb]) << 4));
                }
#pragma unroll
                for (int nb16 = 0; nb16 < 4; ++nb16)
                    ldsm_x4t(bf[nb16], bBase[nb16] + (uint32_t)(k16 * 8192));
#pragma unroll
                for (int mb = 0; mb < 2; ++mb)
#pragma unroll
                    for (int nb = 0; nb < 8; ++nb)
                        mma16816(C[mb][nb], af[mb], &bf[nb >> 1][(nb & 1) * 2]);
            }
            bar_arrive(BAR_EMPTY0 + buf);         // A[buf] free for producer

            // ---- warp-local LayerNorm + permuted store ----
            const int m0 = t * 64;
#pragma unroll
            for (int mb = 0; mb < 2; ++mb)
#pragma unroll
                for (int half = 0; half < 2; ++half) {
                    float s = 0.f, q = 0.f;
#pragma unroll
                    for (int nb = 0; nb < 8; ++nb) {
                        float v0 = C[mb][nb][2 * half];
                        float v1 = C[mb][nb][2 * half + 1];
                        s += v0 + v1;
                        q += v0 * v0 + v1 * v1;
                    }
                    s += __shfl_xor_sync(0xffffffffu, s, 1);
                    q += __shfl_xor_sync(0xffffffffu, q, 1);
                    s += __shfl_xor_sync(0xffffffffu, s, 2);
                    q += __shfl_xor_sync(0xffffffffu, q, 2);
                    const float mu   = s * (1.0f / 64.0f);
                    const float var  = q * (1.0f / 64.0f) - mu * mu;
                    const float rstd = rsqrtf(fmaxf(var, 0.f) + 1e-30f);

                    const int m    = m0 + wm * 32 + mb * 16 + half * 8 + (lane >> 2);
                    const int orow = (m & 15) * Nn + (m >> 4);
                    float* obase = out + (size_t)orow * 256 + head * 64;
#pragma unroll
                    for (int nb = 0; nb < 8; ++nb) {
                        int c = nb * 8 + (lane & 3) * 2;
                        float2 o;
                        o.x = (C[mb][nb][2 * half]     - mu) * rstd * g0[nb] + be0[nb];
                        o.y = (C[mb][nb][2 * half + 1] - mu) * rstd * g1[nb] + be1[nb];
                        __stcs((float2*)(obase + c), o);
                    }
                }
        }
    }
}

// ======================= launch =============================================
extern "C" void kernel_launch(void* const* d_in, const int* in_sizes, int n_in,
                              void* d_out, int out_size)
{
    const float* x  = (const float*)d_in[0];
    const float* Wv = (const float*)d_in[4];
    const float* lg = (const float*)d_in[5];
    const float* lb = (const float*)d_in[6];
    float* out = (float*)d_out;
    (void)in_sizes; (void)n_in; (void)out_size;

    cudaFuncSetAttribute(gemm_ln_kernel,
                         cudaFuncAttributeMaxDynamicSharedMemorySize, SM_TOT);

    convert_b_kernel<<<256, 256>>>(Wv);
    gemm_ln_kernel<<<GRID, 384, SM_TOT>>>(x, lg, lb, out);
}